// round 6
// baseline (speedup 1.0000x reference)
#include <cuda_runtime.h>
#include <cuda_bf16.h>

// L, R: [N, C, H, W] fp32 ; out: [N, C, D, H, W] fp32
// out[n,c,d,h,w] = (w >= d) ? L[n,c,h,w] - R[n,c,h,w-d] : 1.0f
static constexpr int Nn = 2;
static constexpr int Cc = 32;
static constexpr int Hh = 128;
static constexpr int Ww = 256;
static constexpr int Dd = 48;

static constexpr int W4   = Ww / 4;        // 64 float4 per row
static constexpr int NCH  = Nn * Cc * Hh;  // 8192 rows
static constexpr int HW   = Hh * Ww;
static constexpr int HW4  = HW / 4;        // float4 stride between d planes

static constexpr int ROWS_PER_BLOCK = 8;   // 256 threads = 8 rows x 32 threads
                                           // each thread: 8 consecutive floats

__global__ __launch_bounds__(256)
void cost_volume_kernel(const float* __restrict__ L,
                        const float* __restrict__ R,
                        float* __restrict__ out)
{
    // Shared staging of 8 R rows: 8 x 256 floats = 8 KB.
    __shared__ float4 rsh[ROWS_PER_BLOCK][W4];

    const int tid = threadIdx.x;
    const int wt  = tid & 31;                  // 0..31 within row
    const int rin = tid >> 5;                  // row within block, 0..7
    const int row = blockIdx.x * ROWS_PER_BLOCK + rin;   // 0..8191
    const int h   = row & (Hh - 1);
    const int nc  = row >> 7;

    const int p0 = 2 * wt;                     // float4 index of thread's w
    const int w  = p0 * 4;                     // 0..248, thread owns w..w+7

    const float4* __restrict__ rrow4 =
        reinterpret_cast<const float4*>(R + (size_t)row * Ww);
    const float4* __restrict__ lrow4 =
        reinterpret_cast<const float4*>(L + (size_t)row * Ww);

    // Stage R row into shared: two perfectly coalesced passes per warp.
    rsh[rin][wt]      = __ldg(rrow4 + wt);
    rsh[rin][wt + 32] = __ldg(rrow4 + wt + 32);

    // L operands: two float4, reused for all 48 disparities.
    float4 lv0 = __ldg(lrow4 + p0);
    float4 lv1 = __ldg(lrow4 + p0 + 1);
    __syncthreads();

    float4* outp = reinterpret_cast<float4*>(
        out + ((size_t)(nc * Dd) * Hh + h) * (size_t)Ww + w);

    // Sliding window over the shared R row.
    // Group g handles d = 4g..4g+3. Position p (float4 granularity) uses the
    // 8-float window {A[p-g-1], A[p-g]} with A = rsh[rin].
    // Chain: u = A[p0-g+1], v = A[p0-g]; each iter load t = A[p0-g-1].
    float4 u = rsh[rin][p0 + 1];               // A[p1 - 0]
    float4 v = rsh[rin][p0];                   // A[p0 - 0]

    #pragma unroll
    for (int g = 0; g < Dd / 4; ++g) {
        int jt = p0 - g - 1;
        jt = jt < 0 ? 0 : jt;                  // clamp; garbage masked by (w>=d)
        float4 t = rsh[rin][jt];

        #pragma unroll
        for (int dd = 0; dd < 4; ++dd) {
            const int d = 4 * g + dd;

            // pos0: window {t, v} -> r[w+k-d] = win0[4+k-dd]
            float win0[8] = {t.x, t.y, t.z, t.w, v.x, v.y, v.z, v.w};
            float4 o0;
            o0.x = (w + 0 >= d) ? (lv0.x - win0[4 + 0 - dd]) : 1.0f;
            o0.y = (w + 1 >= d) ? (lv0.y - win0[5 - dd])     : 1.0f;
            o0.z = (w + 2 >= d) ? (lv0.z - win0[6 - dd])     : 1.0f;
            o0.w = (w + 3 >= d) ? (lv0.w - win0[7 - dd])     : 1.0f;

            // pos1: window {v, u} -> r[w+4+k-d] = win1[4+k-dd]
            float win1[8] = {v.x, v.y, v.z, v.w, u.x, u.y, u.z, u.w};
            float4 o1;
            o1.x = (w + 4 >= d) ? (lv1.x - win1[4 + 0 - dd]) : 1.0f;
            o1.y = (w + 5 >= d) ? (lv1.y - win1[5 - dd])     : 1.0f;
            o1.z = (w + 6 >= d) ? (lv1.z - win1[6 - dd])     : 1.0f;
            o1.w = (w + 7 >= d) ? (lv1.w - win1[7 - dd])     : 1.0f;

            // Two adjacent STG.128 -> warp writes 1 KB contiguous per d;
            // block writes 8 KB contiguous per d. Evict-first streaming.
            __stcs(outp + (size_t)d * HW4,     o0);
            __stcs(outp + (size_t)d * HW4 + 1, o1);
        }

        u = v;                                 // slide window left by 4
        v = t;
    }
}

extern "C" void kernel_launch(void* const* d_in, const int* in_sizes, int n_in,
                              void* d_out, int out_size)
{
    const float* L = (const float*)d_in[0];
    const float* R = (const float*)d_in[1];
    float* out = (float*)d_out;

    const int block = 256;
    const int grid  = NCH / ROWS_PER_BLOCK;   // 1024 blocks, exact
    cost_volume_kernel<<<grid, block>>>(L, R, out);
}

// round 7
// speedup vs baseline: 2.1489x; 2.1489x over previous
#include <cuda_runtime.h>
#include <cuda_bf16.h>

// L, R: [N, C, H, W] fp32 ; out: [N, C, D, H, W] fp32
// out[n,c,d,h,w] = (w >= d) ? L[n,c,h,w] - R[n,c,h,w-d] : 1.0f
static constexpr int Nn = 2;
static constexpr int Cc = 32;
static constexpr int Hh = 128;
static constexpr int Ww = 256;
static constexpr int Dd = 48;

static constexpr int W4   = Ww / 4;        // 64 float4 per row
static constexpr int NCH  = Nn * Cc * Hh;  // 8192 rows
static constexpr int HW   = Hh * Ww;
static constexpr int HW4  = HW / 4;        // float4 stride between d planes

static constexpr int DCHUNK = 12;              // disparities per register window
static constexpr int WINF4  = DCHUNK / 4 + 2;  // 5 float4 = 20 floats

__global__ __launch_bounds__(256)
void cost_volume_kernel(const float* __restrict__ L,
                        const float* __restrict__ R,
                        float* __restrict__ out)
{
    int tid = blockIdx.x * 256 + threadIdx.x;   // exact grid: NCH*W4 threads
    int w4  = tid & (W4 - 1);                   // 0..63
    int row = tid >> 6;                         // 0..8191
    int h   = row & (Hh - 1);
    int nc  = row >> 7;

    int w = w4 * 4;

    const float4* __restrict__ rrow4 =
        reinterpret_cast<const float4*>(R + (size_t)row * Ww);

    // L operand: one LDG.128, reused for all 48 disparities.
    float4 lv = __ldg(reinterpret_cast<const float4*>(L + (size_t)row * Ww) + w4);

    float4* outp = reinterpret_cast<float4*>(
        out + ((size_t)(nc * Dd) * Hh + h) * (size_t)Ww + w);

    #pragma unroll
    for (int c = 0; c < Dd; c += DCHUNK) {
        // Register window over r[w-c-(DCHUNK-4) .. w-c+7] : WINF4 aligned
        // float4 loads (L2-resident). Clamped addresses produce garbage that
        // the (w>=d) predicate masks to 1.0.
        float win[4 * WINF4];
        #pragma unroll
        for (int j = 0; j < WINF4; ++j) {
            int idx = w4 - (c >> 2) - (WINF4 - 2) + j;
            idx = idx < 0 ? 0 : idx;
            float4 v = __ldg(rrow4 + idx);
            win[4 * j + 0] = v.x;
            win[4 * j + 1] = v.y;
            win[4 * j + 2] = v.z;
            win[4 * j + 3] = v.w;
        }

        // Element r[w+k-d] (d = c+dd) lives at win[BASE + k - dd];
        // indices are compile-time after unrolling -> window stays in regs.
        constexpr int BASE = 4 * (WINF4 - 2);

        #pragma unroll
        for (int dd = 0; dd < DCHUNK; ++dd) {
            const int d = c + dd;
            float4 o;
            o.x = (w + 0 >= d) ? (lv.x - win[BASE + 0 - dd]) : 1.0f;
            o.y = (w + 1 >= d) ? (lv.y - win[BASE + 1 - dd]) : 1.0f;
            o.z = (w + 2 >= d) ? (lv.z - win[BASE + 2 - dd]) : 1.0f;
            o.w = (w + 3 >= d) ? (lv.w - win[BASE + 3 - dd]) : 1.0f;
            // Streaming store: evict-first in L2 (zero-reuse output stream).
            __stcs(outp + (size_t)d * HW4, o);
        }
    }
}

extern "C" void kernel_launch(void* const* d_in, const int* in_sizes, int n_in,
                              void* d_out, int out_size)
{
    const float* L = (const float*)d_in[0];
    const float* R = (const float*)d_in[1];
    float* out = (float*)d_out;

    const int total_threads = NCH * W4;       // 524,288
    const int block = 256;
    const int grid  = total_threads / block;  // 2048
    cost_volume_kernel<<<grid, block>>>(L, R, out);
}